// round 13
// baseline (speedup 1.0000x reference)
#include <cuda_runtime.h>
#include <cuda_fp16.h>
#include <mma.h>
#include <math.h>

using namespace nvcuda;

#define NN 50000
#define NE 800000
#define HD 64
#define EDIM 32
#define FULLM 0xffffffffu
#define SCAN_NB 49

// ---------------- device scratch ----------------
__device__ __half2 g_h2[NN * 32];   // node transform, half2 packed
__device__ float  g_x1[NN * HD];
__device__ float  g_x2[NN * HD];
__device__ __half2 g_A2[NN * 32];
__device__ __half2 g_B2[NN * 32];
__device__ float  g_ssrc[NN];
__device__ float  g_sdst[NN];
__device__ float2 g_se[NE];         // per-edge {se1, se2}, linear
__device__ int    g_deg[NN + 1];    // [NN] doubles as grid-barrier counter
__device__ int    g_off[NN + 1];
__device__ int    g_cursor[NN];
__device__ float4 g_csr[NE];        // {bitcast(src), se1, se2, ssrc1}
__device__ int    g_bsum[64];

__device__ __forceinline__ float lrelu(float z) { return z > 0.f ? z : 0.2f * z; }

// ---------------- streaming pass: degree + se1/se2, smem-transposed ea reads ----------------
__global__ __launch_bounds__(256) void k_deg_se(
    const int* __restrict__ ei, const float* __restrict__ ea,
    const float* __restrict__ We1, const float* __restrict__ ae1,
    const float* __restrict__ We2, const float* __restrict__ ae2)
{
    __shared__ float we[2][EDIM];
    __shared__ float sx[256][EDIM + 1];
    int tid = threadIdx.x;
    if (tid < 64) {
        const float* We = (tid < 32) ? We1 : We2;
        const float* ae = (tid < 32) ? ae1 : ae2;
        int k = tid & 31;
        float s = 0.f;
        #pragma unroll 8
        for (int j = 0; j < HD; ++j) s += We[k * HD + j] * ae[j];
        we[tid >> 5][k] = s;
    }
    __syncthreads();

    int e0 = blockIdx.x * 256;
    const float4* ea4 = (const float4*)(ea + (size_t)e0 * EDIM);
    #pragma unroll
    for (int it = 0; it < 8; ++it) {
        int idx = it * 256 + tid;
        float4 v = ea4[idx];
        int e = idx >> 3;
        int k = (idx & 7) * 4;
        sx[e][k + 0] = v.x;
        sx[e][k + 1] = v.y;
        sx[e][k + 2] = v.z;
        sx[e][k + 3] = v.w;
    }
    __syncthreads();

    float s1 = 0.f, s2 = 0.f;
    #pragma unroll
    for (int k = 0; k < EDIM; ++k) {
        float v = sx[tid][k];
        s1 = fmaf(v, we[0][k], s1);
        s2 = fmaf(v, we[1][k], s2);
    }
    g_se[e0 + tid] = make_float2(s1, s2);
    atomicAdd(&g_deg[ei[NE + e0 + tid]], 1);
}

// ---------------- single-kernel scan (grid barrier over 49 resident blocks) ----------------
__global__ __launch_bounds__(1024) void k_scan_all() {
    int t = threadIdx.x, lane = t & 31, warp = t >> 5;
    int i = blockIdx.x * 1024 + t;
    int v = (i < NN) ? g_deg[i] : 0;
    int x = v;
    #pragma unroll
    for (int o = 1; o < 32; o <<= 1) {
        int y = __shfl_up_sync(FULLM, x, o);
        if (lane >= o) x += y;
    }
    __shared__ int ws[32];
    if (lane == 31) ws[warp] = x;
    __syncthreads();
    if (warp == 0) {
        int s = ws[lane];
        #pragma unroll
        for (int o = 1; o < 32; o <<= 1) {
            int y = __shfl_up_sync(FULLM, s, o);
            if (lane >= o) s += y;
        }
        ws[lane] = s;
    }
    __syncthreads();
    int local_excl = x - v + (warp ? ws[warp - 1] : 0);
    if (t == 1023) g_bsum[blockIdx.x] = local_excl + v;
    __threadfence();
    __syncthreads();
    if (t == 0) {
        atomicAdd(&g_deg[NN], 1);
        while (atomicAdd(&g_deg[NN], 0) < SCAN_NB) { }
    }
    __syncthreads();
    __shared__ int s_carry;
    if (warp == 0) {
        int c = 0;
        for (int j = lane; j < blockIdx.x; j += 32) c += __ldcg(&g_bsum[j]);
        #pragma unroll
        for (int o = 16; o > 0; o >>= 1) c += __shfl_xor_sync(FULLM, c, o);
        if (lane == 0) s_carry = c;
    }
    __syncthreads();
    if (i < NN) {
        int o = local_excl + s_carry;
        g_off[i] = o;
        g_cursor[i] = o;
    }
    if (i == 0) g_off[NN] = NE;
}

// ---------------- lean CSR scatter: 4 edges/thread; embeds ssrc1 in payload.w ----------------
__global__ __launch_bounds__(256) void k_scatter(const int* __restrict__ ei) {
    int base = blockIdx.x * 1024 + threadIdx.x;
    #pragma unroll
    for (int k = 0; k < 4; ++k) {
        int e = base + k * 256;
        if (e < NE) {
            int src = ei[e];
            int dst = ei[NE + e];
            float2 se = g_se[e];
            float ss1 = g_ssrc[src];
            int pos = atomicAdd(&g_cursor[dst], 1);
            g_csr[pos] = make_float4(__int_as_float(src), se.x, se.y, ss1);
        }
    }
}

// ---------------- node GEMM: 64 rows/block, 8 rows/thread ----------------
template <int DIN, bool DOS, bool ZDEG>
__global__ __launch_bounds__(256) void k_gemm(
    const float* __restrict__ x, const float* __restrict__ W,
    const float* __restrict__ as_, const float* __restrict__ ad_,
    __half2* __restrict__ h2, float* __restrict__ ssrc, float* __restrict__ sdst)
{
    __shared__ float xs[64][DIN];
    int tx = threadIdx.x, ty = threadIdx.y;
    int tid = ty * 32 + tx;
    int n0 = blockIdx.x * 64;
    if (ZDEG && tid < 64) {
        int di = n0 + tid;
        if (di <= NN) g_deg[di] = 0;
    }
    int nrows = NN - n0; if (nrows > 64) nrows = 64;
    int tot4 = nrows * DIN / 4;
    const float4* xg = (const float4*)(x + (size_t)n0 * DIN);
    float4* xs4 = (float4*)&xs[0][0];
    for (int idx = tid; idx < tot4; idx += 256) xs4[idx] = xg[idx];
    __syncthreads();

    float a0[8] = {0,0,0,0,0,0,0,0};
    float a1[8] = {0,0,0,0,0,0,0,0};
    #pragma unroll
    for (int k4 = 0; k4 < DIN / 4; ++k4) {
        float2 w[4];
        #pragma unroll
        for (int q = 0; q < 4; ++q)
            w[q] = *(const float2*)&W[(4 * k4 + q) * HD + 2 * tx];
        #pragma unroll
        for (int r = 0; r < 8; ++r) {
            float4 v = ((const float4*)&xs[ty * 8 + r][0])[k4];
            a0[r] = fmaf(v.x, w[0].x, a0[r]); a1[r] = fmaf(v.x, w[0].y, a1[r]);
            a0[r] = fmaf(v.y, w[1].x, a0[r]); a1[r] = fmaf(v.y, w[1].y, a1[r]);
            a0[r] = fmaf(v.z, w[2].x, a0[r]); a1[r] = fmaf(v.z, w[2].y, a1[r]);
            a0[r] = fmaf(v.w, w[3].x, a0[r]); a1[r] = fmaf(v.w, w[3].y, a1[r]);
        }
    }
    float2 av, dv;
    if (DOS) {
        av = *(const float2*)&as_[2 * tx];
        dv = *(const float2*)&ad_[2 * tx];
    }
    #pragma unroll
    for (int r = 0; r < 8; ++r) {
        int n = n0 + ty * 8 + r;
        if (n >= NN) break;
        h2[(size_t)n * 32 + tx] = __floats2half2_rn(a0[r], a1[r]);
        if (DOS) {
            float v1 = a0[r] * av.x + a1[r] * av.y;
            float v2 = a0[r] * dv.x + a1[r] * dv.y;
            #pragma unroll
            for (int o = 16; o > 0; o >>= 1) {
                v1 += __shfl_xor_sync(FULLM, v1, o);
                v2 += __shfl_xor_sync(FULLM, v2, o);
            }
            if (tx == 0) { ssrc[n] = v1; sdst[n] = v2; }
        }
    }
}

// classifier node transform: A = x2@Wc1[0:64], B = x2@Wc1[64:128], half2 out
__global__ __launch_bounds__(256) void k_gemm_cls(
    const float* __restrict__ x, const float* __restrict__ Wc1,
    __half2* __restrict__ A2, __half2* __restrict__ B2)
{
    __shared__ float xs[32][HD];
    int tx = threadIdx.x, ty = threadIdx.y;
    int tid = ty * 32 + tx;
    int n0 = blockIdx.x * 32;
    int nrows = NN - n0; if (nrows > 32) nrows = 32;
    int tot4 = nrows * HD / 4;
    const float4* xg = (const float4*)(x + (size_t)n0 * HD);
    float4* xs4 = (float4*)&xs[0][0];
    for (int idx = tid; idx < tot4; idx += 256) xs4[idx] = xg[idx];
    __syncthreads();

    float a0[4] = {0,0,0,0}, a1[4] = {0,0,0,0};
    float c0[4] = {0,0,0,0}, c1[4] = {0,0,0,0};
    #pragma unroll
    for (int k4 = 0; k4 < HD / 4; ++k4) {
        float2 wa[4], wb[4];
        #pragma unroll
        for (int q = 0; q < 4; ++q) {
            int k = 4 * k4 + q;
            wa[q] = *(const float2*)&Wc1[(size_t)k * HD + 2 * tx];
            wb[q] = *(const float2*)&Wc1[(size_t)(HD + k) * HD + 2 * tx];
        }
        #pragma unroll
        for (int r = 0; r < 4; ++r) {
            float4 v = ((const float4*)&xs[ty * 4 + r][0])[k4];
            a0[r] = fmaf(v.x, wa[0].x, a0[r]); a1[r] = fmaf(v.x, wa[0].y, a1[r]);
            c0[r] = fmaf(v.x, wb[0].x, c0[r]); c1[r] = fmaf(v.x, wb[0].y, c1[r]);
            a0[r] = fmaf(v.y, wa[1].x, a0[r]); a1[r] = fmaf(v.y, wa[1].y, a1[r]);
            c0[r] = fmaf(v.y, wb[1].x, c0[r]); c1[r] = fmaf(v.y, wb[1].y, c1[r]);
            a0[r] = fmaf(v.z, wa[2].x, a0[r]); a1[r] = fmaf(v.z, wa[2].y, a1[r]);
            c0[r] = fmaf(v.z, wb[2].x, c0[r]); c1[r] = fmaf(v.z, wb[2].y, c1[r]);
            a0[r] = fmaf(v.w, wa[3].x, a0[r]); a1[r] = fmaf(v.w, wa[3].y, a1[r]);
            c0[r] = fmaf(v.w, wb[3].x, c0[r]); c1[r] = fmaf(v.w, wb[3].y, c1[r]);
        }
    }
    #pragma unroll
    for (int r = 0; r < 4; ++r) {
        int n = n0 + ty * 4 + r;
        if (n >= NN) break;
        A2[(size_t)n * 32 + tx] = __floats2half2_rn(a0[r], a1[r]);
        B2[(size_t)n * 32 + tx] = __floats2half2_rn(c0[r], c1[r]);
    }
}

// ---------------- attention: no-max softmax, full warp per dst, unroll-4 batched loads ----------------
// L==0 reads ssrc from csr payload .w (embedded at scatter); L==1 gathers g_ssrc.
template <int L>
__global__ __launch_bounds__(256) void k_attn(
    const __half2* __restrict__ h2, const float* __restrict__ bias, float* __restrict__ xout)
{
    int n = (blockIdx.x * blockDim.x + threadIdx.x) >> 5;
    int lane = threadIdx.x & 31;
    if (n >= NN) return;
    int beg = g_off[n], end = g_off[n + 1];
    float sdn = g_sdst[n];
    float ssn = g_ssrc[n];

    float denomA = 0.f, denomB = 0.f;
    float acc0A = 0.f, acc1A = 0.f, acc0B = 0.f, acc1B = 0.f;
    float sumse = 0.f;

    int i = beg;
    for (; i + 3 < end; i += 4) {
        float4 c0 = g_csr[i];
        float4 c1 = g_csr[i + 1];
        float4 c2 = g_csr[i + 2];
        float4 c3 = g_csr[i + 3];
        int s0 = __float_as_int(c0.x);
        int s1 = __float_as_int(c1.x);
        int s2 = __float_as_int(c2.x);
        int s3 = __float_as_int(c3.x);
        float ss0 = (L == 0) ? c0.w : g_ssrc[s0];
        float ss1 = (L == 0) ? c1.w : g_ssrc[s1];
        float ss2 = (L == 0) ? c2.w : g_ssrc[s2];
        float ss3 = (L == 0) ? c3.w : g_ssrc[s3];
        float2 h0 = __half22float2(h2[(size_t)s0 * 32 + lane]);
        float2 h1 = __half22float2(h2[(size_t)s1 * 32 + lane]);
        float2 h2v = __half22float2(h2[(size_t)s2 * 32 + lane]);
        float2 h3 = __half22float2(h2[(size_t)s3 * 32 + lane]);
        float se0 = (L == 0) ? c0.y : c0.z;
        float se1 = (L == 0) ? c1.y : c1.z;
        float se2 = (L == 0) ? c2.y : c2.z;
        float se3 = (L == 0) ? c3.y : c3.z;
        sumse += (se0 + se1) + (se2 + se3);
        float ex0 = __expf(lrelu(ss0 + sdn + se0));
        float ex1 = __expf(lrelu(ss1 + sdn + se1));
        float ex2 = __expf(lrelu(ss2 + sdn + se2));
        float ex3 = __expf(lrelu(ss3 + sdn + se3));
        denomA += ex0 + ex2; denomB += ex1 + ex3;
        acc0A = fmaf(ex0, h0.x, acc0A);  acc1A = fmaf(ex0, h0.y, acc1A);
        acc0B = fmaf(ex1, h1.x, acc0B);  acc1B = fmaf(ex1, h1.y, acc1B);
        acc0A = fmaf(ex2, h2v.x, acc0A); acc1A = fmaf(ex2, h2v.y, acc1A);
        acc0B = fmaf(ex3, h3.x, acc0B);  acc1B = fmaf(ex3, h3.y, acc1B);
    }
    for (; i < end; ++i) {
        float4 c0 = g_csr[i];
        int   s0 = __float_as_int(c0.x);
        float se0 = (L == 0) ? c0.y : c0.z;
        float ss0 = (L == 0) ? c0.w : g_ssrc[s0];
        sumse += se0;
        float ex0 = __expf(lrelu(ss0 + sdn + se0));
        float2 h0 = __half22float2(h2[(size_t)s0 * 32 + lane]);
        denomA += ex0;
        acc0A = fmaf(ex0, h0.x, acc0A);
        acc1A = fmaf(ex0, h0.y, acc1A);
    }
    // self loop (edge attr = mean of incoming se)
    int deg = end - beg;
    float ls = lrelu(ssn + sdn + sumse / fmaxf((float)deg, 1.f));
    float es = __expf(ls);
    float2 hn = __half22float2(h2[(size_t)n * 32 + lane]);
    float denom = denomA + denomB + es;
    float acc0 = acc0A + acc0B + es * hn.x;
    float acc1 = acc1A + acc1B + es * hn.y;

    float inv = 1.f / denom;
    float2 bv = *(const float2*)&bias[2 * lane];
    float2 o = make_float2(fmaxf(acc0 * inv + bv.x, 0.f), fmaxf(acc1 * inv + bv.y, 0.f));
    *(float2*)&xout[(size_t)n * HD + 2 * lane] = o;
}

// ---------------- edge classifier: split-fp16 tensor-core ea@Wc1c + scalar epilogue ----------------
__global__ __launch_bounds__(256) void k_edge_out(
    const __half2* __restrict__ A2, const __half2* __restrict__ B2,
    const int* __restrict__ ei, const float* __restrict__ ea,
    const float* __restrict__ Wc1, const float* __restrict__ bc1,
    const float* __restrict__ Wc2, const float* __restrict__ bc2,
    float* __restrict__ out)
{
    __shared__ __half sa_hi[128][EDIM];   // 8KB
    __shared__ __half sa_lo[128][EDIM];   // 8KB
    __shared__ __half sw_hi[EDIM][HD];    // 4KB
    __shared__ __half sw_lo[EDIM][HD];    // 4KB
    __shared__ float  sc[128][HD];        // 32KB
    int tid = threadIdx.x, lane = tid & 31, wy = tid >> 5;
    int e0 = blockIdx.x * 128;

    float2 bp = *(const float2*)&bc1[2 * lane];
    float2 cp = *(const float2*)&Wc2[2 * lane];
    float bias2 = bc2[0];

    // stage weight slice Wc1 rows [2HD, 2HD+32) as hi+lo fp16
    for (int idx = tid; idx < EDIM * HD; idx += 256) {
        int k = idx >> 6, nn = idx & 63;
        float v = Wc1[(size_t)(2 * HD + k) * HD + nn];
        __half hi = __float2half_rn(v);
        sw_hi[k][nn] = hi;
        sw_lo[k][nn] = __float2half_rn(v - __half2float(hi));
    }
    // stage 128 edges of ea as hi+lo fp16
    const float4* ea4 = (const float4*)(ea + (size_t)e0 * EDIM);
    for (int idx = tid; idx < 128 * 8; idx += 256) {
        int e = idx >> 3, qq = (idx & 7) * 4;
        float4 v = ea4[idx];
        float vv[4] = {v.x, v.y, v.z, v.w};
        #pragma unroll
        for (int j = 0; j < 4; ++j) {
            __half hi = __float2half_rn(vv[j]);
            sa_hi[e][qq + j] = hi;
            sa_lo[e][qq + j] = __float2half_rn(vv[j] - __half2float(hi));
        }
    }
    __syncthreads();

    // per-warp HMMA: 16 edges x 64 outputs; C = hi*Whi + lo*Whi + hi*Wlo
    {
        wmma::fragment<wmma::matrix_a, 16, 16, 16, __half, wmma::row_major> ah0, ah1, al0, al1;
        wmma::load_matrix_sync(ah0, &sa_hi[wy * 16][0],  EDIM);
        wmma::load_matrix_sync(ah1, &sa_hi[wy * 16][16], EDIM);
        wmma::load_matrix_sync(al0, &sa_lo[wy * 16][0],  EDIM);
        wmma::load_matrix_sync(al1, &sa_lo[wy * 16][16], EDIM);
        #pragma unroll
        for (int nt = 0; nt < 4; ++nt) {
            wmma::fragment<wmma::accumulator, 16, 16, 16, float> cf;
            wmma::fill_fragment(cf, 0.f);
            wmma::fragment<wmma::matrix_b, 16, 16, 16, __half, wmma::row_major> bf;
            wmma::load_matrix_sync(bf, &sw_hi[0][nt * 16], HD);
            wmma::mma_sync(cf, ah0, bf, cf);
            wmma::mma_sync(cf, al0, bf, cf);
            wmma::load_matrix_sync(bf, &sw_hi[16][nt * 16], HD);
            wmma::mma_sync(cf, ah1, bf, cf);
            wmma::mma_sync(cf, al1, bf, cf);
            wmma::load_matrix_sync(bf, &sw_lo[0][nt * 16], HD);
            wmma::mma_sync(cf, ah0, bf, cf);
            wmma::load_matrix_sync(bf, &sw_lo[16][nt * 16], HD);
            wmma::mma_sync(cf, ah1, bf, cf);
            wmma::store_matrix_sync(&sc[wy * 16][nt * 16], cf, HD, wmma::mem_row_major);
        }
    }
    __syncwarp();

    // epilogue: relu(A[r]+B[c]+C+bc1) . Wc2, warp-reduced
    #pragma unroll 1
    for (int j = 0; j < 16; j += 2) {
        int le1 = wy * 16 + j, le2 = le1 + 1;
        int e1 = e0 + le1, e2 = e0 + le2;
        int r1 = ei[e1], c1 = ei[NE + e1];
        int r2 = ei[e2], c2 = ei[NE + e2];
        float2 Ar1 = __half22float2(A2[(size_t)r1 * 32 + lane]);
        float2 Bc1_ = __half22float2(B2[(size_t)c1 * 32 + lane]);
        float2 Ar2 = __half22float2(A2[(size_t)r2 * 32 + lane]);
        float2 Bc2_ = __half22float2(B2[(size_t)c2 * 32 + lane]);
        float2 C1 = *(const float2*)&sc[le1][2 * lane];
        float2 C2 = *(const float2*)&sc[le2][2 * lane];
        float p1 = fmaxf(C1.x + Ar1.x + Bc1_.x + bp.x, 0.f) * cp.x
                 + fmaxf(C1.y + Ar1.y + Bc1_.y + bp.y, 0.f) * cp.y;
        float p2 = fmaxf(C2.x + Ar2.x + Bc2_.x + bp.x, 0.f) * cp.x
                 + fmaxf(C2.y + Ar2.y + Bc2_.y + bp.y, 0.f) * cp.y;
        #pragma unroll
        for (int o = 16; o > 0; o >>= 1) {
            p1 += __shfl_xor_sync(FULLM, p1, o);
            p2 += __shfl_xor_sync(FULLM, p2, o);
        }
        if (lane == 0) {
            out[e1] = p1 + bias2;
            out[e2] = p2 + bias2;
        }
    }
}

// ---------------- launch (single stream) ----------------
extern "C" void kernel_launch(void* const* d_in, const int* in_sizes, int n_in,
                              void* d_out, int out_size) {
    const float* x   = (const float*)d_in[0];
    const int*   ei  = (const int*)  d_in[1];
    const float* ea  = (const float*)d_in[2];
    const float* W1  = (const float*)d_in[3];
    const float* We1 = (const float*)d_in[4];
    const float* as1 = (const float*)d_in[5];
    const float* ad1 = (const float*)d_in[6];
    const float* ae1 = (const float*)d_in[7];
    const float* b1  = (const float*)d_in[8];
    const float* W2  = (const float*)d_in[9];
    const float* We2 = (const float*)d_in[10];
    const float* as2 = (const float*)d_in[11];
    const float* ad2 = (const float*)d_in[12];
    const float* ae2 = (const float*)d_in[13];
    const float* b2  = (const float*)d_in[14];
    const float* Wc1 = (const float*)d_in[15];
    const float* bc1 = (const float*)d_in[16];
    const float* Wc2 = (const float*)d_in[17];
    const float* bc2 = (const float*)d_in[18];
    float* out = (float*)d_out;

    void* p;
    cudaGetSymbolAddress(&p, g_h2);   __half2* ph  = (__half2*)p;
    cudaGetSymbolAddress(&p, g_x1);   float* px1 = (float*)p;
    cudaGetSymbolAddress(&p, g_x2);   float* px2 = (float*)p;
    cudaGetSymbolAddress(&p, g_A2);   __half2* pA = (__half2*)p;
    cudaGetSymbolAddress(&p, g_B2);   __half2* pB = (__half2*)p;
    cudaGetSymbolAddress(&p, g_ssrc); float* pss = (float*)p;
    cudaGetSymbolAddress(&p, g_sdst); float* psd = (float*)p;

    dim3 gblk(32, 8);
    int gemm_grid = (NN + 63) / 64;
    int cls_grid  = (NN + 31) / 32;

    // layer-1 node GEMM first; its blocks also zero g_deg (no memset launch)
    k_gemm<128, true, true><<<gemm_grid, gblk>>>(x, W1, as1, ad1, ph, pss, psd);

    k_deg_se<<<NE / 256, 256>>>(ei, ea, We1, ae1, We2, ae2);
    k_scan_all<<<SCAN_NB, 1024>>>();
    k_scatter<<<(NE + 1023) / 1024, 256>>>(ei);

    // layer 1 aggregation
    k_attn<0><<<NN / 8, 256>>>(ph, b1, px1);

    // layer 2
    k_gemm<64, true, false><<<gemm_grid, gblk>>>(px1, W2, as2, ad2, ph, pss, psd);
    k_attn<1><<<NN / 8, 256>>>(ph, b2, px2);

    // classifier
    k_gemm_cls<<<cls_grid, gblk>>>(px2, Wc1, pA, pB);
    k_edge_out<<<NE / 128, 256>>>(pA, pB, ei, ea, Wc1, bc1, Wc2, bc2, out);
}

// round 14
// speedup vs baseline: 1.1440x; 1.1440x over previous
#include <cuda_runtime.h>
#include <cuda_fp16.h>
#include <mma.h>
#include <math.h>

using namespace nvcuda;

#define NN 50000
#define NE 800000
#define HD 64
#define EDIM 32
#define FULLM 0xffffffffu
#define SCAN_NB 49

// ---------------- device scratch ----------------
__device__ __half2 g_h2[NN * 32];   // node transform, half2 packed
__device__ float  g_x1[NN * HD];
__device__ float  g_x2[NN * HD];
__device__ __half2 g_A2[NN * 32];
__device__ __half2 g_B2[NN * 32];
__device__ float  g_ssrc[NN];
__device__ float  g_sdst[NN];
__device__ float2 g_se[NE];         // per-edge {se1, se2}, linear
__device__ int    g_deg[NN + 1];    // [NN] doubles as grid-barrier counter
__device__ int    g_off[NN + 1];
__device__ int    g_cursor[NN];
__device__ float4 g_csr[NE];        // {bitcast(src), se1, se2, ssrc1}
__device__ int    g_bsum[64];

__device__ __forceinline__ float lrelu(float z) { return z > 0.f ? z : 0.2f * z; }

// ---------------- streaming pass: degree + se1/se2, smem-transposed ea reads ----------------
__global__ __launch_bounds__(256) void k_deg_se(
    const int* __restrict__ ei, const float* __restrict__ ea,
    const float* __restrict__ We1, const float* __restrict__ ae1,
    const float* __restrict__ We2, const float* __restrict__ ae2)
{
    __shared__ float we[2][EDIM];
    __shared__ float sx[256][EDIM + 1];
    int tid = threadIdx.x;
    if (tid < 64) {
        const float* We = (tid < 32) ? We1 : We2;
        const float* ae = (tid < 32) ? ae1 : ae2;
        int k = tid & 31;
        float s = 0.f;
        #pragma unroll 8
        for (int j = 0; j < HD; ++j) s += We[k * HD + j] * ae[j];
        we[tid >> 5][k] = s;
    }
    __syncthreads();

    int e0 = blockIdx.x * 256;
    const float4* ea4 = (const float4*)(ea + (size_t)e0 * EDIM);
    #pragma unroll
    for (int it = 0; it < 8; ++it) {
        int idx = it * 256 + tid;
        float4 v = ea4[idx];
        int e = idx >> 3;
        int k = (idx & 7) * 4;
        sx[e][k + 0] = v.x;
        sx[e][k + 1] = v.y;
        sx[e][k + 2] = v.z;
        sx[e][k + 3] = v.w;
    }
    __syncthreads();

    float s1 = 0.f, s2 = 0.f;
    #pragma unroll
    for (int k = 0; k < EDIM; ++k) {
        float v = sx[tid][k];
        s1 = fmaf(v, we[0][k], s1);
        s2 = fmaf(v, we[1][k], s2);
    }
    g_se[e0 + tid] = make_float2(s1, s2);
    atomicAdd(&g_deg[ei[NE + e0 + tid]], 1);
}

// ---------------- single-kernel scan (grid barrier over 49 resident blocks) ----------------
__global__ __launch_bounds__(1024) void k_scan_all() {
    int t = threadIdx.x, lane = t & 31, warp = t >> 5;
    int i = blockIdx.x * 1024 + t;
    int v = (i < NN) ? g_deg[i] : 0;
    int x = v;
    #pragma unroll
    for (int o = 1; o < 32; o <<= 1) {
        int y = __shfl_up_sync(FULLM, x, o);
        if (lane >= o) x += y;
    }
    __shared__ int ws[32];
    if (lane == 31) ws[warp] = x;
    __syncthreads();
    if (warp == 0) {
        int s = ws[lane];
        #pragma unroll
        for (int o = 1; o < 32; o <<= 1) {
            int y = __shfl_up_sync(FULLM, s, o);
            if (lane >= o) s += y;
        }
        ws[lane] = s;
    }
    __syncthreads();
    int local_excl = x - v + (warp ? ws[warp - 1] : 0);
    if (t == 1023) g_bsum[blockIdx.x] = local_excl + v;
    __threadfence();
    __syncthreads();
    if (t == 0) {
        atomicAdd(&g_deg[NN], 1);
        while (atomicAdd(&g_deg[NN], 0) < SCAN_NB) { }
    }
    __syncthreads();
    __shared__ int s_carry;
    if (warp == 0) {
        int c = 0;
        for (int j = lane; j < blockIdx.x; j += 32) c += __ldcg(&g_bsum[j]);
        #pragma unroll
        for (int o = 16; o > 0; o >>= 1) c += __shfl_xor_sync(FULLM, c, o);
        if (lane == 0) s_carry = c;
    }
    __syncthreads();
    if (i < NN) {
        int o = local_excl + s_carry;
        g_off[i] = o;
        g_cursor[i] = o;
    }
    if (i == 0) g_off[NN] = NE;
}

// ---------------- lean CSR scatter: 4 edges/thread; embeds ssrc1 in payload.w ----------------
__global__ __launch_bounds__(256) void k_scatter(const int* __restrict__ ei) {
    int base = blockIdx.x * 1024 + threadIdx.x;
    #pragma unroll
    for (int k = 0; k < 4; ++k) {
        int e = base + k * 256;
        if (e < NE) {
            int src = ei[e];
            int dst = ei[NE + e];
            float2 se = g_se[e];
            float ss1 = g_ssrc[src];
            int pos = atomicAdd(&g_cursor[dst], 1);
            g_csr[pos] = make_float4(__int_as_float(src), se.x, se.y, ss1);
        }
    }
}

// ---------------- node GEMM: 64 rows/block, 8 rows/thread ----------------
template <int DIN, bool DOS, bool ZDEG>
__global__ __launch_bounds__(256) void k_gemm(
    const float* __restrict__ x, const float* __restrict__ W,
    const float* __restrict__ as_, const float* __restrict__ ad_,
    __half2* __restrict__ h2, float* __restrict__ ssrc, float* __restrict__ sdst)
{
    __shared__ float xs[64][DIN];
    int tx = threadIdx.x, ty = threadIdx.y;
    int tid = ty * 32 + tx;
    int n0 = blockIdx.x * 64;
    if (ZDEG && tid < 64) {
        int di = n0 + tid;
        if (di <= NN) g_deg[di] = 0;
    }
    int nrows = NN - n0; if (nrows > 64) nrows = 64;
    int tot4 = nrows * DIN / 4;
    const float4* xg = (const float4*)(x + (size_t)n0 * DIN);
    float4* xs4 = (float4*)&xs[0][0];
    for (int idx = tid; idx < tot4; idx += 256) xs4[idx] = xg[idx];
    __syncthreads();

    float a0[8] = {0,0,0,0,0,0,0,0};
    float a1[8] = {0,0,0,0,0,0,0,0};
    #pragma unroll
    for (int k4 = 0; k4 < DIN / 4; ++k4) {
        float2 w[4];
        #pragma unroll
        for (int q = 0; q < 4; ++q)
            w[q] = *(const float2*)&W[(4 * k4 + q) * HD + 2 * tx];
        #pragma unroll
        for (int r = 0; r < 8; ++r) {
            float4 v = ((const float4*)&xs[ty * 8 + r][0])[k4];
            a0[r] = fmaf(v.x, w[0].x, a0[r]); a1[r] = fmaf(v.x, w[0].y, a1[r]);
            a0[r] = fmaf(v.y, w[1].x, a0[r]); a1[r] = fmaf(v.y, w[1].y, a1[r]);
            a0[r] = fmaf(v.z, w[2].x, a0[r]); a1[r] = fmaf(v.z, w[2].y, a1[r]);
            a0[r] = fmaf(v.w, w[3].x, a0[r]); a1[r] = fmaf(v.w, w[3].y, a1[r]);
        }
    }
    float2 av, dv;
    if (DOS) {
        av = *(const float2*)&as_[2 * tx];
        dv = *(const float2*)&ad_[2 * tx];
    }
    #pragma unroll
    for (int r = 0; r < 8; ++r) {
        int n = n0 + ty * 8 + r;
        if (n >= NN) break;
        h2[(size_t)n * 32 + tx] = __floats2half2_rn(a0[r], a1[r]);
        if (DOS) {
            float v1 = a0[r] * av.x + a1[r] * av.y;
            float v2 = a0[r] * dv.x + a1[r] * dv.y;
            #pragma unroll
            for (int o = 16; o > 0; o >>= 1) {
                v1 += __shfl_xor_sync(FULLM, v1, o);
                v2 += __shfl_xor_sync(FULLM, v2, o);
            }
            if (tx == 0) { ssrc[n] = v1; sdst[n] = v2; }
        }
    }
}

// classifier node transform: A = x2@Wc1[0:64], B = x2@Wc1[64:128], half2 out
__global__ __launch_bounds__(256) void k_gemm_cls(
    const float* __restrict__ x, const float* __restrict__ Wc1,
    __half2* __restrict__ A2, __half2* __restrict__ B2)
{
    __shared__ float xs[32][HD];
    int tx = threadIdx.x, ty = threadIdx.y;
    int tid = ty * 32 + tx;
    int n0 = blockIdx.x * 32;
    int nrows = NN - n0; if (nrows > 32) nrows = 32;
    int tot4 = nrows * HD / 4;
    const float4* xg = (const float4*)(x + (size_t)n0 * HD);
    float4* xs4 = (float4*)&xs[0][0];
    for (int idx = tid; idx < tot4; idx += 256) xs4[idx] = xg[idx];
    __syncthreads();

    float a0[4] = {0,0,0,0}, a1[4] = {0,0,0,0};
    float c0[4] = {0,0,0,0}, c1[4] = {0,0,0,0};
    #pragma unroll
    for (int k4 = 0; k4 < HD / 4; ++k4) {
        float2 wa[4], wb[4];
        #pragma unroll
        for (int q = 0; q < 4; ++q) {
            int k = 4 * k4 + q;
            wa[q] = *(const float2*)&Wc1[(size_t)k * HD + 2 * tx];
            wb[q] = *(const float2*)&Wc1[(size_t)(HD + k) * HD + 2 * tx];
        }
        #pragma unroll
        for (int r = 0; r < 4; ++r) {
            float4 v = ((const float4*)&xs[ty * 4 + r][0])[k4];
            a0[r] = fmaf(v.x, wa[0].x, a0[r]); a1[r] = fmaf(v.x, wa[0].y, a1[r]);
            c0[r] = fmaf(v.x, wb[0].x, c0[r]); c1[r] = fmaf(v.x, wb[0].y, c1[r]);
            a0[r] = fmaf(v.y, wa[1].x, a0[r]); a1[r] = fmaf(v.y, wa[1].y, a1[r]);
            c0[r] = fmaf(v.y, wb[1].x, c0[r]); c1[r] = fmaf(v.y, wb[1].y, c1[r]);
            a0[r] = fmaf(v.z, wa[2].x, a0[r]); a1[r] = fmaf(v.z, wa[2].y, a1[r]);
            c0[r] = fmaf(v.z, wb[2].x, c0[r]); c1[r] = fmaf(v.z, wb[2].y, c1[r]);
            a0[r] = fmaf(v.w, wa[3].x, a0[r]); a1[r] = fmaf(v.w, wa[3].y, a1[r]);
            c0[r] = fmaf(v.w, wb[3].x, c0[r]); c1[r] = fmaf(v.w, wb[3].y, c1[r]);
        }
    }
    #pragma unroll
    for (int r = 0; r < 4; ++r) {
        int n = n0 + ty * 4 + r;
        if (n >= NN) break;
        A2[(size_t)n * 32 + tx] = __floats2half2_rn(a0[r], a1[r]);
        B2[(size_t)n * 32 + tx] = __floats2half2_rn(c0[r], c1[r]);
    }
}

// ---------------- attention: no-max softmax, full warp per dst, unroll-4 batched loads ----------------
// L==0 reads ssrc from csr payload .w (embedded at scatter); L==1 gathers g_ssrc.
template <int L>
__global__ __launch_bounds__(256) void k_attn(
    const __half2* __restrict__ h2, const float* __restrict__ bias, float* __restrict__ xout)
{
    int n = (blockIdx.x * blockDim.x + threadIdx.x) >> 5;
    int lane = threadIdx.x & 31;
    if (n >= NN) return;
    int beg = g_off[n], end = g_off[n + 1];
    float sdn = g_sdst[n];
    float ssn = g_ssrc[n];

    float denomA = 0.f, denomB = 0.f;
    float acc0A = 0.f, acc1A = 0.f, acc0B = 0.f, acc1B = 0.f;
    float sumse = 0.f;

    int i = beg;
    for (; i + 3 < end; i += 4) {
        float4 c0 = g_csr[i];
        float4 c1 = g_csr[i + 1];
        float4 c2 = g_csr[i + 2];
        float4 c3 = g_csr[i + 3];
        int s0 = __float_as_int(c0.x);
        int s1 = __float_as_int(c1.x);
        int s2 = __float_as_int(c2.x);
        int s3 = __float_as_int(c3.x);
        float ss0 = (L == 0) ? c0.w : g_ssrc[s0];
        float ss1 = (L == 0) ? c1.w : g_ssrc[s1];
        float ss2 = (L == 0) ? c2.w : g_ssrc[s2];
        float ss3 = (L == 0) ? c3.w : g_ssrc[s3];
        float2 h0 = __half22float2(h2[(size_t)s0 * 32 + lane]);
        float2 h1 = __half22float2(h2[(size_t)s1 * 32 + lane]);
        float2 h2v = __half22float2(h2[(size_t)s2 * 32 + lane]);
        float2 h3 = __half22float2(h2[(size_t)s3 * 32 + lane]);
        float se0 = (L == 0) ? c0.y : c0.z;
        float se1 = (L == 0) ? c1.y : c1.z;
        float se2 = (L == 0) ? c2.y : c2.z;
        float se3 = (L == 0) ? c3.y : c3.z;
        sumse += (se0 + se1) + (se2 + se3);
        float ex0 = __expf(lrelu(ss0 + sdn + se0));
        float ex1 = __expf(lrelu(ss1 + sdn + se1));
        float ex2 = __expf(lrelu(ss2 + sdn + se2));
        float ex3 = __expf(lrelu(ss3 + sdn + se3));
        denomA += ex0 + ex2; denomB += ex1 + ex3;
        acc0A = fmaf(ex0, h0.x, acc0A);  acc1A = fmaf(ex0, h0.y, acc1A);
        acc0B = fmaf(ex1, h1.x, acc0B);  acc1B = fmaf(ex1, h1.y, acc1B);
        acc0A = fmaf(ex2, h2v.x, acc0A); acc1A = fmaf(ex2, h2v.y, acc1A);
        acc0B = fmaf(ex3, h3.x, acc0B);  acc1B = fmaf(ex3, h3.y, acc1B);
    }
    for (; i < end; ++i) {
        float4 c0 = g_csr[i];
        int   s0 = __float_as_int(c0.x);
        float se0 = (L == 0) ? c0.y : c0.z;
        float ss0 = (L == 0) ? c0.w : g_ssrc[s0];
        sumse += se0;
        float ex0 = __expf(lrelu(ss0 + sdn + se0));
        float2 h0 = __half22float2(h2[(size_t)s0 * 32 + lane]);
        denomA += ex0;
        acc0A = fmaf(ex0, h0.x, acc0A);
        acc1A = fmaf(ex0, h0.y, acc1A);
    }
    // self loop (edge attr = mean of incoming se)
    int deg = end - beg;
    float ls = lrelu(ssn + sdn + sumse / fmaxf((float)deg, 1.f));
    float es = __expf(ls);
    float2 hn = __half22float2(h2[(size_t)n * 32 + lane]);
    float denom = denomA + denomB + es;
    float acc0 = acc0A + acc0B + es * hn.x;
    float acc1 = acc1A + acc1B + es * hn.y;

    float inv = 1.f / denom;
    float2 bv = *(const float2*)&bias[2 * lane];
    float2 o = make_float2(fmaxf(acc0 * inv + bv.x, 0.f), fmaxf(acc1 * inv + bv.y, 0.f));
    *(float2*)&xout[(size_t)n * HD + 2 * lane] = o;
}

// ---------------- edge classifier: single-fp16 tensor-core ea@Wc1c + scalar epilogue (R11) ----------------
__global__ __launch_bounds__(256) void k_edge_out(
    const __half2* __restrict__ A2, const __half2* __restrict__ B2,
    const int* __restrict__ ei, const float* __restrict__ ea,
    const float* __restrict__ Wc1, const float* __restrict__ bc1,
    const float* __restrict__ Wc2, const float* __restrict__ bc2,
    float* __restrict__ out)
{
    __shared__ __half sa[128][EDIM];   // 8KB: ea tile, fp16
    __shared__ __half sw[EDIM][HD];    // 4KB: Wc1c (32x64), fp16
    __shared__ float  sc[128][HD];     // 32KB: C = ea@Wc1c, fp32
    int tid = threadIdx.x, lane = tid & 31, wy = tid >> 5;
    int e0 = blockIdx.x * 128;

    float2 bp = *(const float2*)&bc1[2 * lane];
    float2 cp = *(const float2*)&Wc2[2 * lane];
    float bias2 = bc2[0];

    // stage weight slice Wc1 rows [2HD, 2HD+32) as fp16
    for (int idx = tid; idx < EDIM * HD; idx += 256) {
        int k = idx >> 6, n = idx & 63;
        sw[k][n] = __float2half(Wc1[(size_t)(2 * HD + k) * HD + n]);
    }
    // stage 128 edges of ea as fp16 (coalesced float4 reads)
    const float4* ea4 = (const float4*)(ea + (size_t)e0 * EDIM);
    for (int idx = tid; idx < 128 * 8; idx += 256) {
        int e = idx >> 3, q = (idx & 7) * 4;
        float4 v = ea4[idx];
        sa[e][q + 0] = __float2half(v.x);
        sa[e][q + 1] = __float2half(v.y);
        sa[e][q + 2] = __float2half(v.z);
        sa[e][q + 3] = __float2half(v.w);
    }
    __syncthreads();

    // per-warp HMMA: 16 edges x 64 outputs
    {
        wmma::fragment<wmma::matrix_a, 16, 16, 16, __half, wmma::row_major> af0, af1;
        wmma::load_matrix_sync(af0, &sa[wy * 16][0],  EDIM);
        wmma::load_matrix_sync(af1, &sa[wy * 16][16], EDIM);
        #pragma unroll
        for (int nt = 0; nt < 4; ++nt) {
            wmma::fragment<wmma::accumulator, 16, 16, 16, float> cf;
            wmma::fill_fragment(cf, 0.f);
            wmma::fragment<wmma::matrix_b, 16, 16, 16, __half, wmma::row_major> bf;
            wmma::load_matrix_sync(bf, &sw[0][nt * 16], HD);
            wmma::mma_sync(cf, af0, bf, cf);
            wmma::load_matrix_sync(bf, &sw[16][nt * 16], HD);
            wmma::mma_sync(cf, af1, bf, cf);
            wmma::store_matrix_sync(&sc[wy * 16][nt * 16], cf, HD, wmma::mem_row_major);
        }
    }
    __syncwarp();

    // epilogue: relu(A[r]+B[c]+C+bc1) . Wc2, warp-reduced
    #pragma unroll 1
    for (int j = 0; j < 16; j += 2) {
        int le1 = wy * 16 + j, le2 = le1 + 1;
        int e1 = e0 + le1, e2 = e0 + le2;
        int r1 = ei[e1], c1 = ei[NE + e1];
        int r2 = ei[e2], c2 = ei[NE + e2];
        float2 Ar1 = __half22float2(A2[(size_t)r1 * 32 + lane]);
        float2 Bc1_ = __half22float2(B2[(size_t)c1 * 32 + lane]);
        float2 Ar2 = __half22float2(A2[(size_t)r2 * 32 + lane]);
        float2 Bc2_ = __half22float2(B2[(size_t)c2 * 32 + lane]);
        float2 C1 = *(const float2*)&sc[le1][2 * lane];
        float2 C2 = *(const float2*)&sc[le2][2 * lane];
        float p1 = fmaxf(C1.x + Ar1.x + Bc1_.x + bp.x, 0.f) * cp.x
                 + fmaxf(C1.y + Ar1.y + Bc1_.y + bp.y, 0.f) * cp.y;
        float p2 = fmaxf(C2.x + Ar2.x + Bc2_.x + bp.x, 0.f) * cp.x
                 + fmaxf(C2.y + Ar2.y + Bc2_.y + bp.y, 0.f) * cp.y;
        #pragma unroll
        for (int o = 16; o > 0; o >>= 1) {
            p1 += __shfl_xor_sync(FULLM, p1, o);
            p2 += __shfl_xor_sync(FULLM, p2, o);
        }
        if (lane == 0) {
            out[e1] = p1 + bias2;
            out[e2] = p2 + bias2;
        }
    }
}

// ---------------- launch (single stream) ----------------
extern "C" void kernel_launch(void* const* d_in, const int* in_sizes, int n_in,
                              void* d_out, int out_size) {
    const float* x   = (const float*)d_in[0];
    const int*   ei  = (const int*)  d_in[1];
    const float* ea  = (const float*)d_in[2];
    const float* W1  = (const float*)d_in[3];
    const float* We1 = (const float*)d_in[4];
    const float* as1 = (const float*)d_in[5];
    const float* ad1 = (const float*)d_in[6];
    const float* ae1 = (const float*)d_in[7];
    const float* b1  = (const float*)d_in[8];
    const float* W2  = (const float*)d_in[9];
    const float* We2 = (const float*)d_in[10];
    const float* as2 = (const float*)d_in[11];
    const float* ad2 = (const float*)d_in[12];
    const float* ae2 = (const float*)d_in[13];
    const float* b2  = (const float*)d_in[14];
    const float* Wc1 = (const float*)d_in[15];
    const float* bc1 = (const float*)d_in[16];
    const float* Wc2 = (const float*)d_in[17];
    const float* bc2 = (const float*)d_in[18];
    float* out = (float*)d_out;

    void* p;
    cudaGetSymbolAddress(&p, g_h2);   __half2* ph  = (__half2*)p;
    cudaGetSymbolAddress(&p, g_x1);   float* px1 = (float*)p;
    cudaGetSymbolAddress(&p, g_x2);   float* px2 = (float*)p;
    cudaGetSymbolAddress(&p, g_A2);   __half2* pA = (__half2*)p;
    cudaGetSymbolAddress(&p, g_B2);   __half2* pB = (__half2*)p;
    cudaGetSymbolAddress(&p, g_ssrc); float* pss = (float*)p;
    cudaGetSymbolAddress(&p, g_sdst); float* psd = (float*)p;

    dim3 gblk(32, 8);
    int gemm_grid = (NN + 63) / 64;
    int cls_grid  = (NN + 31) / 32;

    // layer-1 node GEMM first; its blocks also zero g_deg (no memset launch)
    k_gemm<128, true, true><<<gemm_grid, gblk>>>(x, W1, as1, ad1, ph, pss, psd);

    k_deg_se<<<NE / 256, 256>>>(ei, ea, We1, ae1, We2, ae2);
    k_scan_all<<<SCAN_NB, 1024>>>();
    k_scatter<<<(NE + 1023) / 1024, 256>>>(ei);

    // layer 1 aggregation
    k_attn<0><<<NN / 8, 256>>>(ph, b1, px1);

    // layer 2
    k_gemm<64, true, false><<<gemm_grid, gblk>>>(px1, W2, as2, ad2, ph, pss, psd);
    k_attn<1><<<NN / 8, 256>>>(ph, b2, px2);

    // classifier
    k_gemm_cls<<<cls_grid, gblk>>>(px2, Wc1, pA, pB);
    k_edge_out<<<NE / 128, 256>>>(pA, pB, ei, ea, Wc1, bc1, Wc2, bc2, out);
}

// round 16
// speedup vs baseline: 1.1804x; 1.0318x over previous
#include <cuda_runtime.h>
#include <cuda_fp16.h>
#include <mma.h>
#include <math.h>

using namespace nvcuda;

#define NN 50000
#define NE 800000
#define HD 64
#define EDIM 32
#define FULLM 0xffffffffu
#define SCAN_NB 49

// ---------------- device scratch ----------------
__device__ __half2 g_h2[NN * 32];   // node transform, half2 packed
__device__ float  g_x1[NN * HD];
__device__ float  g_x2[NN * HD];
__device__ __half2 g_A2[NN * 32];
__device__ __half2 g_B2[NN * 32];
__device__ float  g_ssrc[NN];
__device__ float  g_sdst[NN];
__device__ float2 g_se[NE];         // per-edge {se1, se2}, linear
__device__ int    g_deg[NN + 1];    // [NN] doubles as grid-barrier counter
__device__ int    g_off[NN + 1];
__device__ int    g_cursor[NN];
__device__ uint2  g_csr[NE];        // {src, bitcast(half2{se1,se2})} — 8B payload
__device__ int    g_bsum[64];

__device__ __forceinline__ float lrelu(float z) { return z > 0.f ? z : 0.2f * z; }

// bit-cast helpers (no such intrinsics in headers)
__device__ __forceinline__ unsigned h2_bits(__half2 h) {
    return *reinterpret_cast<unsigned*>(&h);
}
__device__ __forceinline__ __half2 bits_h2(unsigned u) {
    return *reinterpret_cast<__half2*>(&u);
}

// ---------------- streaming pass: degree + se1/se2, smem-transposed ea reads ----------------
__global__ __launch_bounds__(256) void k_deg_se(
    const int* __restrict__ ei, const float* __restrict__ ea,
    const float* __restrict__ We1, const float* __restrict__ ae1,
    const float* __restrict__ We2, const float* __restrict__ ae2)
{
    __shared__ float we[2][EDIM];
    __shared__ float sx[256][EDIM + 1];
    int tid = threadIdx.x;
    if (tid < 64) {
        const float* We = (tid < 32) ? We1 : We2;
        const float* ae = (tid < 32) ? ae1 : ae2;
        int k = tid & 31;
        float s = 0.f;
        #pragma unroll 8
        for (int j = 0; j < HD; ++j) s += We[k * HD + j] * ae[j];
        we[tid >> 5][k] = s;
    }
    __syncthreads();

    int e0 = blockIdx.x * 256;
    const float4* ea4 = (const float4*)(ea + (size_t)e0 * EDIM);
    #pragma unroll
    for (int it = 0; it < 8; ++it) {
        int idx = it * 256 + tid;
        float4 v = ea4[idx];
        int e = idx >> 3;
        int k = (idx & 7) * 4;
        sx[e][k + 0] = v.x;
        sx[e][k + 1] = v.y;
        sx[e][k + 2] = v.z;
        sx[e][k + 3] = v.w;
    }
    __syncthreads();

    float s1 = 0.f, s2 = 0.f;
    #pragma unroll
    for (int k = 0; k < EDIM; ++k) {
        float v = sx[tid][k];
        s1 = fmaf(v, we[0][k], s1);
        s2 = fmaf(v, we[1][k], s2);
    }
    g_se[e0 + tid] = make_float2(s1, s2);
    atomicAdd(&g_deg[ei[NE + e0 + tid]], 1);
}

// ---------------- single-kernel scan (grid barrier over 49 resident blocks) ----------------
__global__ __launch_bounds__(1024) void k_scan_all() {
    int t = threadIdx.x, lane = t & 31, warp = t >> 5;
    int i = blockIdx.x * 1024 + t;
    int v = (i < NN) ? g_deg[i] : 0;
    int x = v;
    #pragma unroll
    for (int o = 1; o < 32; o <<= 1) {
        int y = __shfl_up_sync(FULLM, x, o);
        if (lane >= o) x += y;
    }
    __shared__ int ws[32];
    if (lane == 31) ws[warp] = x;
    __syncthreads();
    if (warp == 0) {
        int s = ws[lane];
        #pragma unroll
        for (int o = 1; o < 32; o <<= 1) {
            int y = __shfl_up_sync(FULLM, s, o);
            if (lane >= o) s += y;
        }
        ws[lane] = s;
    }
    __syncthreads();
    int local_excl = x - v + (warp ? ws[warp - 1] : 0);
    if (t == 1023) g_bsum[blockIdx.x] = local_excl + v;
    __threadfence();
    __syncthreads();
    if (t == 0) {
        atomicAdd(&g_deg[NN], 1);
        while (atomicAdd(&g_deg[NN], 0) < SCAN_NB) { }
    }
    __syncthreads();
    __shared__ int s_carry;
    if (warp == 0) {
        int c = 0;
        for (int j = lane; j < blockIdx.x; j += 32) c += __ldcg(&g_bsum[j]);
        #pragma unroll
        for (int o = 16; o > 0; o >>= 1) c += __shfl_xor_sync(FULLM, c, o);
        if (lane == 0) s_carry = c;
    }
    __syncthreads();
    if (i < NN) {
        int o = local_excl + s_carry;
        g_off[i] = o;
        g_cursor[i] = o;
    }
    if (i == 0) g_off[NN] = NE;
}

// ---------------- lean CSR scatter: 8 independent edges per thread, 8B payload ----------------
__global__ __launch_bounds__(256) void k_scatter(const int* __restrict__ ei) {
    int base = blockIdx.x * 2048 + threadIdx.x;
    #pragma unroll
    for (int k = 0; k < 8; ++k) {
        int e = base + k * 256;
        if (e < NE) {
            int src = ei[e];
            int dst = ei[NE + e];
            float2 se = g_se[e];
            __half2 seh = __floats2half2_rn(se.x, se.y);
            int pos = atomicAdd(&g_cursor[dst], 1);
            g_csr[pos] = make_uint2((unsigned)src, h2_bits(seh));
        }
    }
}

// ---------------- node GEMM: 64 rows/block, 8 rows/thread ----------------
template <int DIN, bool DOS, bool ZDEG>
__global__ __launch_bounds__(256) void k_gemm(
    const float* __restrict__ x, const float* __restrict__ W,
    const float* __restrict__ as_, const float* __restrict__ ad_,
    __half2* __restrict__ h2, float* __restrict__ ssrc, float* __restrict__ sdst)
{
    __shared__ float xs[64][DIN];
    int tx = threadIdx.x, ty = threadIdx.y;
    int tid = ty * 32 + tx;
    int n0 = blockIdx.x * 64;
    if (ZDEG && tid < 64) {
        int di = n0 + tid;
        if (di <= NN) g_deg[di] = 0;
    }
    int nrows = NN - n0; if (nrows > 64) nrows = 64;
    int tot4 = nrows * DIN / 4;
    const float4* xg = (const float4*)(x + (size_t)n0 * DIN);
    float4* xs4 = (float4*)&xs[0][0];
    for (int idx = tid; idx < tot4; idx += 256) xs4[idx] = xg[idx];
    __syncthreads();

    float a0[8] = {0,0,0,0,0,0,0,0};
    float a1[8] = {0,0,0,0,0,0,0,0};
    #pragma unroll
    for (int k4 = 0; k4 < DIN / 4; ++k4) {
        float2 w[4];
        #pragma unroll
        for (int q = 0; q < 4; ++q)
            w[q] = *(const float2*)&W[(4 * k4 + q) * HD + 2 * tx];
        #pragma unroll
        for (int r = 0; r < 8; ++r) {
            float4 v = ((const float4*)&xs[ty * 8 + r][0])[k4];
            a0[r] = fmaf(v.x, w[0].x, a0[r]); a1[r] = fmaf(v.x, w[0].y, a1[r]);
            a0[r] = fmaf(v.y, w[1].x, a0[r]); a1[r] = fmaf(v.y, w[1].y, a1[r]);
            a0[r] = fmaf(v.z, w[2].x, a0[r]); a1[r] = fmaf(v.z, w[2].y, a1[r]);
            a0[r] = fmaf(v.w, w[3].x, a0[r]); a1[r] = fmaf(v.w, w[3].y, a1[r]);
        }
    }
    float2 av, dv;
    if (DOS) {
        av = *(const float2*)&as_[2 * tx];
        dv = *(const float2*)&ad_[2 * tx];
    }
    #pragma unroll
    for (int r = 0; r < 8; ++r) {
        int n = n0 + ty * 8 + r;
        if (n >= NN) break;
        h2[(size_t)n * 32 + tx] = __floats2half2_rn(a0[r], a1[r]);
        if (DOS) {
            float v1 = a0[r] * av.x + a1[r] * av.y;
            float v2 = a0[r] * dv.x + a1[r] * dv.y;
            #pragma unroll
            for (int o = 16; o > 0; o >>= 1) {
                v1 += __shfl_xor_sync(FULLM, v1, o);
                v2 += __shfl_xor_sync(FULLM, v2, o);
            }
            if (tx == 0) { ssrc[n] = v1; sdst[n] = v2; }
        }
    }
}

// classifier node transform: A = x2@Wc1[0:64], B = x2@Wc1[64:128], half2 out
__global__ __launch_bounds__(256) void k_gemm_cls(
    const float* __restrict__ x, const float* __restrict__ Wc1,
    __half2* __restrict__ A2, __half2* __restrict__ B2)
{
    __shared__ float xs[32][HD];
    int tx = threadIdx.x, ty = threadIdx.y;
    int tid = ty * 32 + tx;
    int n0 = blockIdx.x * 32;
    int nrows = NN - n0; if (nrows > 32) nrows = 32;
    int tot4 = nrows * HD / 4;
    const float4* xg = (const float4*)(x + (size_t)n0 * HD);
    float4* xs4 = (float4*)&xs[0][0];
    for (int idx = tid; idx < tot4; idx += 256) xs4[idx] = xg[idx];
    __syncthreads();

    float a0[4] = {0,0,0,0}, a1[4] = {0,0,0,0};
    float c0[4] = {0,0,0,0}, c1[4] = {0,0,0,0};
    #pragma unroll
    for (int k4 = 0; k4 < HD / 4; ++k4) {
        float2 wa[4], wb[4];
        #pragma unroll
        for (int q = 0; q < 4; ++q) {
            int k = 4 * k4 + q;
            wa[q] = *(const float2*)&Wc1[(size_t)k * HD + 2 * tx];
            wb[q] = *(const float2*)&Wc1[(size_t)(HD + k) * HD + 2 * tx];
        }
        #pragma unroll
        for (int r = 0; r < 4; ++r) {
            float4 v = ((const float4*)&xs[ty * 4 + r][0])[k4];
            a0[r] = fmaf(v.x, wa[0].x, a0[r]); a1[r] = fmaf(v.x, wa[0].y, a1[r]);
            c0[r] = fmaf(v.x, wb[0].x, c0[r]); c1[r] = fmaf(v.x, wb[0].y, c1[r]);
            a0[r] = fmaf(v.y, wa[1].x, a0[r]); a1[r] = fmaf(v.y, wa[1].y, a1[r]);
            c0[r] = fmaf(v.y, wb[1].x, c0[r]); c1[r] = fmaf(v.y, wb[1].y, c1[r]);
            a0[r] = fmaf(v.z, wa[2].x, a0[r]); a1[r] = fmaf(v.z, wa[2].y, a1[r]);
            c0[r] = fmaf(v.z, wb[2].x, c0[r]); c1[r] = fmaf(v.z, wb[2].y, c1[r]);
            a0[r] = fmaf(v.w, wa[3].x, a0[r]); a1[r] = fmaf(v.w, wa[3].y, a1[r]);
            c0[r] = fmaf(v.w, wb[3].x, c0[r]); c1[r] = fmaf(v.w, wb[3].y, c1[r]);
        }
    }
    #pragma unroll
    for (int r = 0; r < 4; ++r) {
        int n = n0 + ty * 4 + r;
        if (n >= NN) break;
        A2[(size_t)n * 32 + tx] = __floats2half2_rn(a0[r], a1[r]);
        B2[(size_t)n * 32 + tx] = __floats2half2_rn(c0[r], c1[r]);
    }
}

// ---------------- attention: no-max softmax, full warp per dst, unroll-4, 8B csr ----------------
template <int L>
__global__ __launch_bounds__(256) void k_attn(
    const __half2* __restrict__ h2, const float* __restrict__ bias, float* __restrict__ xout)
{
    int n = (blockIdx.x * blockDim.x + threadIdx.x) >> 5;
    int lane = threadIdx.x & 31;
    if (n >= NN) return;
    int beg = g_off[n], end = g_off[n + 1];
    float sdn = g_sdst[n];
    float ssn = g_ssrc[n];

    float denomA = 0.f, denomB = 0.f;
    float acc0A = 0.f, acc1A = 0.f, acc0B = 0.f, acc1B = 0.f;
    float sumse = 0.f;

    int i = beg;
    for (; i + 3 < end; i += 4) {
        uint2 c0 = g_csr[i];
        uint2 c1 = g_csr[i + 1];
        uint2 c2 = g_csr[i + 2];
        uint2 c3 = g_csr[i + 3];
        int s0 = (int)c0.x;
        int s1 = (int)c1.x;
        int s2 = (int)c2.x;
        int s3 = (int)c3.x;
        float ss0 = g_ssrc[s0];
        float ss1 = g_ssrc[s1];
        float ss2 = g_ssrc[s2];
        float ss3 = g_ssrc[s3];
        float2 h0 = __half22float2(h2[(size_t)s0 * 32 + lane]);
        float2 h1 = __half22float2(h2[(size_t)s1 * 32 + lane]);
        float2 h2v = __half22float2(h2[(size_t)s2 * 32 + lane]);
        float2 h3 = __half22float2(h2[(size_t)s3 * 32 + lane]);
        float2 sp0 = __half22float2(bits_h2(c0.y));
        float2 sp1 = __half22float2(bits_h2(c1.y));
        float2 sp2 = __half22float2(bits_h2(c2.y));
        float2 sp3 = __half22float2(bits_h2(c3.y));
        float se0 = (L == 0) ? sp0.x : sp0.y;
        float se1 = (L == 0) ? sp1.x : sp1.y;
        float se2 = (L == 0) ? sp2.x : sp2.y;
        float se3 = (L == 0) ? sp3.x : sp3.y;
        sumse += (se0 + se1) + (se2 + se3);
        float ex0 = __expf(lrelu(ss0 + sdn + se0));
        float ex1 = __expf(lrelu(ss1 + sdn + se1));
        float ex2 = __expf(lrelu(ss2 + sdn + se2));
        float ex3 = __expf(lrelu(ss3 + sdn + se3));
        denomA += ex0 + ex2; denomB += ex1 + ex3;
        acc0A = fmaf(ex0, h0.x, acc0A);  acc1A = fmaf(ex0, h0.y, acc1A);
        acc0B = fmaf(ex1, h1.x, acc0B);  acc1B = fmaf(ex1, h1.y, acc1B);
        acc0A = fmaf(ex2, h2v.x, acc0A); acc1A = fmaf(ex2, h2v.y, acc1A);
        acc0B = fmaf(ex3, h3.x, acc0B);  acc1B = fmaf(ex3, h3.y, acc1B);
    }
    for (; i < end; ++i) {
        uint2 c0 = g_csr[i];
        int   s0 = (int)c0.x;
        float2 sp0 = __half22float2(bits_h2(c0.y));
        float se0 = (L == 0) ? sp0.x : sp0.y;
        sumse += se0;
        float ex0 = __expf(lrelu(g_ssrc[s0] + sdn + se0));
        float2 h0 = __half22float2(h2[(size_t)s0 * 32 + lane]);
        denomA += ex0;
        acc0A = fmaf(ex0, h0.x, acc0A);
        acc1A = fmaf(ex0, h0.y, acc1A);
    }
    // self loop (edge attr = mean of incoming se)
    int deg = end - beg;
    float ls = lrelu(ssn + sdn + sumse / fmaxf((float)deg, 1.f));
    float es = __expf(ls);
    float2 hn = __half22float2(h2[(size_t)n * 32 + lane]);
    float denom = denomA + denomB + es;
    float acc0 = acc0A + acc0B + es * hn.x;
    float acc1 = acc1A + acc1B + es * hn.y;

    float inv = 1.f / denom;
    float2 bv = *(const float2*)&bias[2 * lane];
    float2 o = make_float2(fmaxf(acc0 * inv + bv.x, 0.f), fmaxf(acc1 * inv + bv.y, 0.f));
    *(float2*)&xout[(size_t)n * HD + 2 * lane] = o;
}

// ---------------- edge classifier: single-fp16 tensor-core ea@Wc1c + scalar epilogue (R11) ----------------
__global__ __launch_bounds__(256) void k_edge_out(
    const __half2* __restrict__ A2, const __half2* __restrict__ B2,
    const int* __restrict__ ei, const float* __restrict__ ea,
    const float* __restrict__ Wc1, const float* __restrict__ bc1,
    const float* __restrict__ Wc2, const float* __restrict__ bc2,
    float* __restrict__ out)
{
    __shared__ __half sa[128][EDIM];   // 8KB: ea tile, fp16
    __shared__ __half sw[EDIM][HD];    // 4KB: Wc1c (32x64), fp16
    __shared__ float  sc[128][HD];     // 32KB: C = ea@Wc1c, fp32
    int tid = threadIdx.x, lane = tid & 31, wy = tid >> 5;
    int e0 = blockIdx.x * 128;

    float2 bp = *(const float2*)&bc1[2 * lane];
    float2 cp = *(const float2*)&Wc2[2 * lane];
    float bias2 = bc2[0];

    // stage weight slice Wc1 rows [2HD, 2HD+32) as fp16
    for (int idx = tid; idx < EDIM * HD; idx += 256) {
        int k = idx >> 6, n = idx & 63;
        sw[k][n] = __float2half(Wc1[(size_t)(2 * HD + k) * HD + n]);
    }
    // stage 128 edges of ea as fp16 (coalesced float4 reads)
    const float4* ea4 = (const float4*)(ea + (size_t)e0 * EDIM);
    for (int idx = tid; idx < 128 * 8; idx += 256) {
        int e = idx >> 3, q = (idx & 7) * 4;
        float4 v = ea4[idx];
        sa[e][q + 0] = __float2half(v.x);
        sa[e][q + 1] = __float2half(v.y);
        sa[e][q + 2] = __float2half(v.z);
        sa[e][q + 3] = __float2half(v.w);
    }
    __syncthreads();

    // per-warp HMMA: 16 edges x 64 outputs
    {
        wmma::fragment<wmma::matrix_a, 16, 16, 16, __half, wmma::row_major> af0, af1;
        wmma::load_matrix_sync(af0, &sa[wy * 16][0],  EDIM);
        wmma::load_matrix_sync(af1, &sa[wy * 16][16], EDIM);
        #pragma unroll
        for (int nt = 0; nt < 4; ++nt) {
            wmma::fragment<wmma::accumulator, 16, 16, 16, float> cf;
            wmma::fill_fragment(cf, 0.f);
            wmma::fragment<wmma::matrix_b, 16, 16, 16, __half, wmma::row_major> bf;
            wmma::load_matrix_sync(bf, &sw[0][nt * 16], HD);
            wmma::mma_sync(cf, af0, bf, cf);
            wmma::load_matrix_sync(bf, &sw[16][nt * 16], HD);
            wmma::mma_sync(cf, af1, bf, cf);
            wmma::store_matrix_sync(&sc[wy * 16][nt * 16], cf, HD, wmma::mem_row_major);
        }
    }
    __syncwarp();

    // epilogue: relu(A[r]+B[c]+C+bc1) . Wc2, warp-reduced
    #pragma unroll 1
    for (int j = 0; j < 16; j += 2) {
        int le1 = wy * 16 + j, le2 = le1 + 1;
        int e1 = e0 + le1, e2 = e0 + le2;
        int r1 = ei[e1], c1 = ei[NE + e1];
        int r2 = ei[e2], c2 = ei[NE + e2];
        float2 Ar1 = __half22float2(A2[(size_t)r1 * 32 + lane]);
        float2 Bc1_ = __half22float2(B2[(size_t)c1 * 32 + lane]);
        float2 Ar2 = __half22float2(A2[(size_t)r2 * 32 + lane]);
        float2 Bc2_ = __half22float2(B2[(size_t)c2 * 32 + lane]);
        float2 C1 = *(const float2*)&sc[le1][2 * lane];
        float2 C2 = *(const float2*)&sc[le2][2 * lane];
        float p1 = fmaxf(C1.x + Ar1.x + Bc1_.x + bp.x, 0.f) * cp.x
                 + fmaxf(C1.y + Ar1.y + Bc1_.y + bp.y, 0.f) * cp.y;
        float p2 = fmaxf(C2.x + Ar2.x + Bc2_.x + bp.x, 0.f) * cp.x
                 + fmaxf(C2.y + Ar2.y + Bc2_.y + bp.y, 0.f) * cp.y;
        #pragma unroll
        for (int o = 16; o > 0; o >>= 1) {
            p1 += __shfl_xor_sync(FULLM, p1, o);
            p2 += __shfl_xor_sync(FULLM, p2, o);
        }
        if (lane == 0) {
            out[e1] = p1 + bias2;
            out[e2] = p2 + bias2;
        }
    }
}

// ---------------- launch (single stream) ----------------
extern "C" void kernel_launch(void* const* d_in, const int* in_sizes, int n_in,
                              void* d_out, int out_size) {
    const float* x   = (const float*)d_in[0];
    const int*   ei  = (const int*)  d_in[1];
    const float* ea  = (const float*)d_in[2];
    const float* W1  = (const float*)d_in[3];
    const float* We1 = (const float*)d_in[4];
    const float* as1 = (const float*)d_in[5];
    const float* ad1 = (const float*)d_in[6];
    const float* ae1 = (const float*)d_in[7];
    const float* b1  = (const float*)d_in[8];
    const float* W2  = (const float*)d_in[9];
    const float* We2 = (const float*)d_in[10];
    const float* as2 = (const float*)d_in[11];
    const float* ad2 = (const float*)d_in[12];
    const float* ae2 = (const float*)d_in[13];
    const float* b2  = (const float*)d_in[14];
    const float* Wc1 = (const float*)d_in[15];
    const float* bc1 = (const float*)d_in[16];
    const float* Wc2 = (const float*)d_in[17];
    const float* bc2 = (const float*)d_in[18];
    float* out = (float*)d_out;

    void* p;
    cudaGetSymbolAddress(&p, g_h2);   __half2* ph  = (__half2*)p;
    cudaGetSymbolAddress(&p, g_x1);   float* px1 = (float*)p;
    cudaGetSymbolAddress(&p, g_x2);   float* px2 = (float*)p;
    cudaGetSymbolAddress(&p, g_A2);   __half2* pA = (__half2*)p;
    cudaGetSymbolAddress(&p, g_B2);   __half2* pB = (__half2*)p;
    cudaGetSymbolAddress(&p, g_ssrc); float* pss = (float*)p;
    cudaGetSymbolAddress(&p, g_sdst); float* psd = (float*)p;

    dim3 gblk(32, 8);
    int gemm_grid = (NN + 63) / 64;
    int cls_grid  = (NN + 31) / 32;

    // layer-1 node GEMM first; its blocks also zero g_deg (no memset launch)
    k_gemm<128, true, true><<<gemm_grid, gblk>>>(x, W1, as1, ad1, ph, pss, psd);

    k_deg_se<<<NE / 256, 256>>>(ei, ea, We1, ae1, We2, ae2);
    k_scan_all<<<SCAN_NB, 1024>>>();
    k_scatter<<<(NE + 2047) / 2048, 256>>>(ei);

    // layer 1 aggregation
    k_attn<0><<<NN / 8, 256>>>(ph, b1, px1);

    // layer 2
    k_gemm<64, true, false><<<gemm_grid, gblk>>>(px1, W2, as2, ad2, ph, pss, psd);
    k_attn<1><<<NN / 8, 256>>>(ph, b2, px2);

    // classifier
    k_gemm_cls<<<cls_grid, gblk>>>(px2, Wc1, pA, pB);
    k_edge_out<<<NE / 128, 256>>>(pA, pB, ei, ea, Wc1, bc1, Wc2, bc2, out);
}